// round 16
// baseline (speedup 1.0000x reference)
#include <cuda_runtime.h>
#include <cuda_bf16.h>
#include <cstdint>

#define B_  2
#define S_  2048
#define D_  1024
#define H_  16
#define DK_ 64
#define BS_ (B_*S_)    // 4096
#define HD_ (H_*DK_)   // 1024

// ---------------- scratch (__device__ globals; no allocs allowed) ----------
__device__ __nv_bfloat16 g_xh[3*BS_*D_];   // q,k,v inputs, hi
__device__ __nv_bfloat16 g_xl[3*BS_*D_];   // lo
__device__ __nv_bfloat16 g_wh[3*HD_*D_];   // Wq/Wk/Wv transposed to [n][d], hi
__device__ __nv_bfloat16 g_wl[3*HD_*D_];
__device__ __nv_bfloat16 g_qh[B_*H_*S_*DK_];  // Q proj (pre-scaled 0.125) [bh][s][d]
__device__ __nv_bfloat16 g_ql[B_*H_*S_*DK_];
__device__ __nv_bfloat16 g_kh[B_*H_*S_*DK_];  // K proj [bh][s][d]
__device__ __nv_bfloat16 g_kl[B_*H_*S_*DK_];
__device__ __nv_bfloat16 g_vth[B_*H_*S_*DK_]; // V proj TRANSPOSED [bh][d][s]
__device__ __nv_bfloat16 g_vtl[B_*H_*S_*DK_];
__device__ __nv_bfloat16 g_ah[BS_*HD_];    // attention output [m][j]
__device__ __nv_bfloat16 g_al[BS_*HD_];
__device__ __nv_bfloat16 g_woh[D_*HD_];    // Wo [n][j] (K-major)
__device__ __nv_bfloat16 g_wol[D_*HD_];

// ---------------- helpers ---------------------------------------------------
__device__ __forceinline__ uint32_t smem_u32(const void* p) {
    uint32_t a;
    asm("{ .reg .u64 t; cvta.to.shared.u64 t, %1; cvt.u32.u64 %0, t; }" : "=r"(a) : "l"(p));
    return a;
}
__device__ __forceinline__ void cp16(uint32_t s, const void* g) {
    asm volatile("cp.async.cg.shared.global [%0], [%1], 16;" :: "r"(s), "l"(g) : "memory");
}
__device__ __forceinline__ void ldsm4(uint32_t* r, uint32_t a) {
    asm volatile("ldmatrix.sync.aligned.m8n8.x4.shared.b16 {%0,%1,%2,%3}, [%4];"
                 : "=r"(r[0]), "=r"(r[1]), "=r"(r[2]), "=r"(r[3]) : "r"(a));
}
__device__ __forceinline__ void ldsm2(uint32_t* r, uint32_t a) {
    asm volatile("ldmatrix.sync.aligned.m8n8.x2.shared.b16 {%0,%1}, [%2];"
                 : "=r"(r[0]), "=r"(r[1]) : "r"(a));
}
__device__ __forceinline__ void mma16816(float* d, const uint32_t* a, const uint32_t* b) {
    asm volatile("mma.sync.aligned.m16n8k16.row.col.f32.bf16.bf16.f32 "
                 "{%0,%1,%2,%3}, {%4,%5,%6,%7}, {%8,%9}, {%0,%1,%2,%3};"
                 : "+f"(d[0]), "+f"(d[1]), "+f"(d[2]), "+f"(d[3])
                 : "r"(a[0]), "r"(a[1]), "r"(a[2]), "r"(a[3]), "r"(b[0]), "r"(b[1]));
}
__device__ __forceinline__ unsigned pk2(float a, float b) {
    __nv_bfloat162 t = __floats2bfloat162_rn(a, b);
    return *reinterpret_cast<unsigned*>(&t);
}
__device__ __forceinline__ float resid(float a) {
    return a - __bfloat162float(__float2bfloat16(a));
}

// ---------------- conversion kernels ---------------------------------------
// One launch for q/k/v/Wo hi-lo splits. i indexes float4 elements.
#define N4X (BS_*D_/4)       // 1,048,576 (power of two)
#define N4W (D_*HD_/4)       // 262,144
__global__ void split_all(const float* __restrict__ q, const float* __restrict__ k,
                          const float* __restrict__ v, const float* __restrict__ wo) {
    const int i = blockIdx.x * blockDim.x + threadIdx.x;
    float4 vv;
    uint2* hi;
    uint2* lo;
    int oi;
    if (i < 3 * N4X) {
        const int seg = i >> 20;              // N4X = 2^20
        const int off = i & (N4X - 1);
        const float* in = (seg == 0) ? q : (seg == 1) ? k : v;
        vv = reinterpret_cast<const float4*>(in)[off];
        hi = reinterpret_cast<uint2*>(g_xh);
        lo = reinterpret_cast<uint2*>(g_xl);
        oi = i;
    } else {
        const int j = i - 3 * N4X;
        if (j >= N4W) return;
        vv = reinterpret_cast<const float4*>(wo)[j];
        hi = reinterpret_cast<uint2*>(g_woh);
        lo = reinterpret_cast<uint2*>(g_wol);
        oi = j;
    }
    uint2 uh, ul;
    uh.x = pk2(vv.x, vv.y);               uh.y = pk2(vv.z, vv.w);
    ul.x = pk2(resid(vv.x), resid(vv.y)); ul.y = pk2(resid(vv.z), resid(vv.w));
    hi[oi] = uh;
    lo[oi] = ul;
}

// Wq/Wk/Wv [H][D][DK] -> [mat][H*DK][D] (hi/lo), tiled transpose
__global__ void conv_w(const float* __restrict__ Wq, const float* __restrict__ Wk,
                       const float* __restrict__ Wv) {
    __shared__ float t[32][33];
    const int mat = blockIdx.z >> 4;
    const int h   = blockIdx.z & 15;
    const float* W = (mat == 0) ? Wq : (mat == 1) ? Wk : Wv;
    const int d0 = blockIdx.x * 32, k0 = blockIdx.y * 32;
    const int tx = threadIdx.x, ty = threadIdx.y;
    #pragma unroll
    for (int i = 0; i < 4; i++)
        t[ty + 8*i][tx] = W[h * (D_*DK_) + (d0 + ty + 8*i) * DK_ + k0 + tx];
    __syncthreads();
    #pragma unroll
    for (int i = 0; i < 4; i++) {
        float v = t[tx][ty + 8*i];
        int o = mat * (HD_*D_) + (h * DK_ + k0 + ty + 8*i) * D_ + d0 + tx;
        g_wh[o] = __float2bfloat16(v);
        g_wl[o] = __float2bfloat16(resid(v));
    }
}

// ---------------- warp-MMA split-bf16 GEMM ---------------------------------
#define BK   32
#define NCH  (D_/BK)         // 32
#define ROWB 80
#define TILEB (128*ROWB)     // 10240
#define STAGEB (4*TILEB)     // 40960
#define SMEM_GEMM (2*STAGEB) // 81920

__global__ void __launch_bounds__(256) gemm_mma(const float* __restrict__ bias,
                                                float* __restrict__ outp, int mode)
{
    extern __shared__ __align__(128) char smem[];
    const int tid = threadIdx.x;
    const int z = blockIdx.z;

    const __nv_bfloat16 *Ah, *Al, *Bh, *Bl;
    if (mode == 0) {
        Ah = g_xh + (size_t)z*BS_*D_;  Al = g_xl + (size_t)z*BS_*D_;
        Bh = g_wh + (size_t)z*HD_*D_;  Bl = g_wl + (size_t)z*HD_*D_;
    } else {
        Ah = g_ah; Al = g_al; Bh = g_woh; Bl = g_wol;
    }
    const int n0 = blockIdx.x * 128;
    const int m0 = blockIdx.y * 128;
    const uint32_t sb = smem_u32(smem);

    const int lane = tid & 31, wid = tid >> 5;
    const int wr = wid >> 2, wc = wid & 3;
    const int lr = lane & 7, lq = lane >> 3;

    float acc[4][4][4];
    #pragma unroll
    for (int mi = 0; mi < 4; mi++)
        #pragma unroll
        for (int ni = 0; ni < 4; ni++)
            #pragma unroll
            for (int r = 0; r < 4; r++) acc[mi][ni][r] = 0.f;

    #define ISSUE(c) do {                                                     \
        const uint32_t st = sb + ((c) & 1) * STAGEB;                          \
        const int k0 = (c) * BK;                                              \
        _Pragma("unroll")                                                     \
        for (int it = 0; it < 2; it++) {                                      \
            const int e = tid + it * 256;                                     \
            const int row = e >> 2, c16 = e & 3;                              \
            const uint32_t so = row * ROWB + c16 * 16;                        \
            cp16(st + so,           Ah + (size_t)(m0+row)*D_ + k0 + c16*8);   \
            cp16(st + TILEB + so,   Al + (size_t)(m0+row)*D_ + k0 + c16*8);   \
            cp16(st + 2*TILEB + so, Bh + (size_t)(n0+row)*D_ + k0 + c16*8);   \
            cp16(st + 3*TILEB + so, Bl + (size_t)(n0+row)*D_ + k0 + c16*8);   \
        }                                                                     \
        asm volatile("cp.async.commit_group;" ::: "memory");                  \
    } while (0)

    ISSUE(0);
    ISSUE(1);

    #pragma unroll 1
    for (int c = 0; c < NCH; c++) {
        if (c < NCH - 1) asm volatile("cp.async.wait_group 1;" ::: "memory");
        else             asm volatile("cp.async.wait_group 0;" ::: "memory");
        __syncthreads();
        const uint32_t st = sb + (c & 1) * STAGEB;

        #pragma unroll
        for (int ks = 0; ks < 2; ks++) {
            uint32_t ah[4][4], al[4][4];
            #pragma unroll
            for (int mi = 0; mi < 4; mi++) {
                const int arow = wr*64 + mi*16 + (lq & 1)*8 + lr;
                const uint32_t aoff = (uint32_t)(arow*ROWB + (ks*16 + (lq >> 1)*8)*2);
                ldsm4(ah[mi], st + aoff);
                ldsm4(al[mi], st + TILEB + aoff);
            }
            #pragma unroll
            for (int ni = 0; ni < 4; ni++) {
                const int brow = wc*32 + ni*8 + lr;
                const uint32_t boff = (uint32_t)(brow*ROWB + (ks*16 + (lq & 1)*8)*2);
                uint32_t bh[2], bl[2];
                ldsm2(bh, st + 2*TILEB + boff);
                ldsm2(bl, st + 3*TILEB + boff);
                #pragma unroll
                for (int mi = 0; mi < 4; mi++) {
                    mma16816(acc[mi][ni], ah[mi], bh);
                    mma16816(acc[mi][ni], ah[mi], bl);
                    mma16816(acc[mi][ni], al[mi], bh);
                }
            }
        }
        __syncthreads();
        if (c + 2 < NCH) ISSUE(c + 2);
    }

    // ---- epilogue ----------------------------------------------------------
    const float sc = (mode == 0 && z == 0) ? 0.125f : 1.f;
    #pragma unroll
    for (int mi = 0; mi < 4; mi++) {
        const int row = m0 + wr*64 + mi*16 + (lane >> 2);
        #pragma unroll
        for (int ni = 0; ni < 4; ni++) {
            const int col = n0 + wc*32 + ni*8 + (lane & 3)*2;
            float c0 = acc[mi][ni][0]*sc, c1 = acc[mi][ni][1]*sc;
            float c2 = acc[mi][ni][2]*sc, c3 = acc[mi][ni][3]*sc;
            if (mode == 0) {
                const int b = row >> 11, s = row & (S_-1);
                const int h = col >> 6, d = col & 63;
                if (z < 2) {
                    __nv_bfloat16* Ph = (z == 0) ? g_qh : g_kh;
                    __nv_bfloat16* Pl = (z == 0) ? g_ql : g_kl;
                    const size_t off = ((size_t)(b*H_ + h)*S_ + s)*DK_ + d;
                    *reinterpret_cast<unsigned*>(Ph + off) = pk2(c0, c1);
                    *reinterpret_cast<unsigned*>(Pl + off) = pk2(resid(c0), resid(c1));
                    *reinterpret_cast<unsigned*>(Ph + off + 8*DK_) = pk2(c2, c3);
                    *reinterpret_cast<unsigned*>(Pl + off + 8*DK_) = pk2(resid(c2), resid(c3));
                } else {
                    // V transposed: [bh][d][s]
                    const size_t base = ((size_t)(b*H_ + h)*DK_ + d)*S_ + s;
                    g_vth[base]        = __float2bfloat16(c0);
                    g_vtl[base]        = __float2bfloat16(resid(c0));
                    g_vth[base + S_]   = __float2bfloat16(c1);
                    g_vtl[base + S_]   = __float2bfloat16(resid(c1));
                    g_vth[base + 8]    = __float2bfloat16(c2);
                    g_vtl[base + 8]    = __float2bfloat16(resid(c2));
                    g_vth[base + S_+8] = __float2bfloat16(c3);
                    g_vtl[base + S_+8] = __float2bfloat16(resid(c3));
                }
            } else {
                float2 bv = *reinterpret_cast<const float2*>(&bias[col]);
                float2 v0 = make_float2(c0 + bv.x, c1 + bv.y);
                float2 v1 = make_float2(c2 + bv.x, c3 + bv.y);
                *reinterpret_cast<float2*>(&outp[(size_t)row*D_ + col]) = v0;
                *reinterpret_cast<float2*>(&outp[(size_t)(row+8)*D_ + col]) = v1;
            }
        }
    }
}

// ---------------- tensor-core causal flash attention -----------------------
// 3-stage cp.async pipeline; FIXED tail-wait: at iteration b only
// rem = nb-1-b groups are newer than b, so allowed-incomplete = min(2, rem).
#define VROW 144
#define KTILE (64*VROW)          // 9216
#define ASTAGE (4*KTILE)         // 36864
#define NSTG 3
#define SMEM_ATT (NSTG*ASTAGE)   // 110592

__global__ void __launch_bounds__(256) attn_mma()
{
    extern __shared__ __align__(128) char smem[];
    const uint32_t sb = smem_u32(smem);
    const int tid = threadIdx.x, lane = tid & 31, wid = tid >> 5;
    const int lr = lane & 7, lq = lane >> 3;
    const int qt = gridDim.x - 1 - blockIdx.x;   // LPT: heavy tiles first
    const int bh = blockIdx.y;
    const int q0 = qt * 128;
    const size_t hb = (size_t)bh * S_ * DK_;
    const __nv_bfloat16* Qh = g_qh + hb;
    const __nv_bfloat16* Ql = g_ql + hb;
    const __nv_bfloat16* Kh = g_kh + hb;
    const __nv_bfloat16* Kl = g_kl + hb;
    const __nv_bfloat16* Vh = g_vth + hb;   // [64][S]
    const __nv_bfloat16* Vl = g_vtl + hb;

    const int nb = 2*qt + 2;

    // ---- stage Q tile (hi/lo) through smem, build A fragments -------------
    #pragma unroll
    for (int it = 0; it < 4; it++) {
        const int e = tid + it * 256;
        const int row = e >> 3, c16 = e & 7;
        uint4 vh = *reinterpret_cast<const uint4*>(Qh + (size_t)(q0+row)*DK_ + c16*8);
        uint4 vl = *reinterpret_cast<const uint4*>(Ql + (size_t)(q0+row)*DK_ + c16*8);
        *reinterpret_cast<uint4*>(smem + row*VROW + c16*16) = vh;
        *reinterpret_cast<uint4*>(smem + 128*VROW + row*VROW + c16*16) = vl;
    }
    __syncthreads();
    uint32_t qa[4][4], qal[4][4];
    {
        const int arow = wid*16 + (lq & 1)*8 + lr;
        #pragma unroll
        for (int ks = 0; ks < 4; ks++) {
            const uint32_t aoff = (uint32_t)(arow*VROW + (ks*16 + (lq >> 1)*8)*2);
            ldsm4(qa[ks],  sb + aoff);
            ldsm4(qal[ks], sb + 128*VROW + aoff);
        }
    }
    __syncthreads();

    float o[8][4];
    #pragma unroll
    for (int ni = 0; ni < 8; ni++)
        #pragma unroll
        for (int r = 0; r < 4; r++) o[ni][r] = 0.f;
    float m0 = -1e30f, m1 = -1e30f, l0 = 0.f, l1 = 0.f;

    const int qtop = q0 + wid*16;
    const int r0 = qtop + (lane >> 2);
    const int r1 = r0 + 8;

    #define AISSUE(bb_) do {                                                  \
        const uint32_t st_ = sb + ((bb_) % NSTG) * ASTAGE;                    \
        const int k0_ = (bb_) * 64;                                           \
        _Pragma("unroll")                                                     \
        for (int it = 0; it < 2; it++) {                                      \
            const int e = tid + it * 256;                                     \
            const int row = e >> 3, c16 = e & 7;                              \
            const uint32_t so = row*VROW + c16*16;                            \
            cp16(st_ + so,           Kh + (size_t)(k0_+row)*DK_ + c16*8);     \
            cp16(st_ + KTILE + so,   Kl + (size_t)(k0_+row)*DK_ + c16*8);     \
            cp16(st_ + 2*KTILE + so, Vh + (size_t)row*S_ + k0_ + c16*8);      \
            cp16(st_ + 3*KTILE + so, Vl + (size_t)row*S_ + k0_ + c16*8);      \
        }                                                                     \
        asm volatile("cp.async.commit_group;" ::: "memory");                  \
    } while (0)

    AISSUE(0);
    if (nb > 1) AISSUE(1);
    if (nb > 2) AISSUE(2);

    #pragma unroll 1
    for (int b = 0; b < nb; b++) {
        // groups newer than b: rem = nb-1-b (capped by issue distance 2).
        // group b is complete iff allowed-incomplete <= rem.
        const int rem = nb - 1 - b;
        if (rem >= 2)      asm volatile("cp.async.wait_group 2;" ::: "memory");
        else if (rem == 1) asm volatile("cp.async.wait_group 1;" ::: "memory");
        else               asm volatile("cp.async.wait_group 0;" ::: "memory");
        __syncthreads();

        if (b*64 <= qtop + 15) {
            const uint32_t st = sb + (b % NSTG) * ASTAGE;

            // ---- S = Q K^T -------------------------------------------------
            float sacc[8][4];
            #pragma unroll
            for (int ni = 0; ni < 8; ni++)
                #pragma unroll
                for (int r = 0; r < 4; r++) sacc[ni][r] = 0.f;

            #pragma unroll
            for (int ni = 0; ni < 8; ni++) {
                const uint32_t brow = ni*8 + lr;
                #pragma unroll
                for (int ks = 0; ks < 4; ks++) {
                    const uint32_t boff = brow*VROW + (ks*16 + (lq & 1)*8)*2;
                    uint32_t kb[2], kbl[2];
                    ldsm2(kb,  st + boff);
                    ldsm2(kbl, st + KTILE + boff);
                    mma16816(sacc[ni], qa[ks],  kb);
                    mma16816(sacc[ni], qa[ks],  kbl);
                    mma16816(sacc[ni], qal[ks], kb);
                }
            }

            // ---- causal mask (diagonal block only) -------------------------
            if (b*64 + 63 > qtop) {
                #pragma unroll
                for (int ni = 0; ni < 8; ni++) {
                    const int c = b*64 + ni*8 + (lane & 3)*2;
                    if (c     > r0) sacc[ni][0] = -1e30f;
                    if (c + 1 > r0) sacc[ni][1] = -1e30f;
                    if (c     > r1) sacc[ni][2] = -1e30f;
                    if (c + 1 > r1) sacc[ni][3] = -1e30f;
                }
            }

            // ---- online softmax -------------------------------------------
            float tm0 = -1e30f, tm1 = -1e30f;
            #pragma unroll
            for (int ni = 0; ni < 8; ni++) {
                tm0 = fmaxf(tm0, fmaxf(sacc[ni][0], sacc[ni][1]));
                tm1 = fmaxf(tm1, fmaxf(sacc[ni][2], sacc[ni][3]));
            }
            #pragma unroll
            for (int off = 1; off < 4; off <<= 1) {
                tm0 = fmaxf(tm0, __shfl_xor_sync(0xffffffffu, tm0, off));
                tm1 = fmaxf(tm1, __shfl_xor_sync(0xffffffffu, tm1, off));
            }
            const float mn0 = fmaxf(m0, tm0), mn1 = fmaxf(m1, tm1);
            const float cr0 = __expf(m0 - mn0), cr1 = __expf(m1 - mn1);
            float rs0 = 0.f, rs1 = 0.f;
            #pragma unroll
            for (int ni = 0; ni < 8; ni++) {
                sacc[ni][0] = __expf(sacc[ni][0] - mn0);
                sacc[ni][1] = __expf(sacc[ni][1] - mn0);
                sacc[ni][2] = __expf(sacc[ni][2] - mn1);
                sacc[ni][3] = __expf(sacc[ni][3] - mn1);
                rs0 += sacc[ni][0] + sacc[ni][1];
                rs1 += sacc[ni][2] + sacc[ni][3];
            }
            #pragma unroll
            for (int off = 1; off < 4; off <<= 1) {
                rs0 += __shfl_xor_sync(0xffffffffu, rs0, off);
                rs1 += __shfl_xor_sync(0xffffffffu, rs1, off);
            }
            l0 = l0*cr0 + rs0;  l1 = l1*cr1 + rs1;
            m0 = mn0;           m1 = mn1;
            #pragma unroll
            for (int ni = 0; ni < 8; ni++) {
                o[ni][0] *= cr0; o[ni][1] *= cr0;
                o[ni][2] *= cr1; o[ni][3] *= cr1;
            }

            // ---- pack P (S-acc layout == A-frag layout) -------------------
            uint32_t pa[4][4], pal[4][4];
            #pragma unroll
            for (int kc = 0; kc < 4; kc++) {
                const float* t0 = sacc[2*kc];
                const float* t1 = sacc[2*kc + 1];
                pa[kc][0]  = pk2(t0[0], t0[1]);
                pa[kc][1]  = pk2(t0[2], t0[3]);
                pa[kc][2]  = pk2(t1[0], t1[1]);
                pa[kc][3]  = pk2(t1[2], t1[3]);
                pal[kc][0] = pk2(resid(t0[0]), resid(t0[1]));
                pal[kc][1] = pk2(resid(t0[2]), resid(t0[3]));
                pal[kc][2] = pk2(resid(t1[0]), resid(t1[1]));
                pal[kc][3] = pk2(resid(t1[2]), resid(t1[3]));
            }

            // ---- O += P V  (B = V^T tile [d][keys]) -----------------------
            #pragma unroll
            for (int ni = 0; ni < 8; ni++) {
                const uint32_t brow = ni*8 + lr;
                #pragma unroll
                for (int kc = 0; kc < 4; kc++) {
                    const uint32_t boff = brow*VROW + (kc*16 + (lq & 1)*8)*2;
                    uint32_t vb[2], vbl[2];
                    ldsm2(vb,  st + 2*KTILE + boff);
                    ldsm2(vbl, st + 3*KTILE + boff);
                    mma16816(o[ni], pa[kc],  vb);
                    mma16816(o[ni], pa[kc],  vbl);
                    mma16816(o[ni], pal[kc], vb);
                }
            }
        }

        __syncthreads();   // all warps done reading stage (b % NSTG)
        if (b + 3 < nb) AISSUE(b + 3);
    }

    // ---- epilogue: O/l -> bf16 hi/lo into [m][j] for oproj ----------------
    const float i0 = 1.f / l0, i1 = 1.f / l1;
    const int bb = bh >> 4, h = bh & 15;
    const size_t mg = (size_t)bb * S_ + r0;
    #pragma unroll
    for (int ni = 0; ni < 8; ni++) {
        const int j = h*64 + ni*8 + (lane & 3)*2;
        float a0 = o[ni][0]*i0, a1 = o[ni][1]*i0;
        float b0 = o[ni][2]*i1, b1 = o[ni][3]*i1;
        *reinterpret_cast<unsigned*>(g_ah + mg*HD_ + j)       = pk2(a0, a1);
        *reinterpret_cast<unsigned*>(g_al + mg*HD_ + j)       = pk2(resid(a0), resid(a1));
        *reinterpret_cast<unsigned*>(g_ah + (mg+8)*HD_ + j)   = pk2(b0, b1);
        *reinterpret_cast<unsigned*>(g_al + (mg+8)*HD_ + j)   = pk2(resid(b0), resid(b1));
    }
}

// ---------------- launch ----------------------------------------------------
extern "C" void kernel_launch(void* const* d_in, const int* in_sizes, int n_in,
                              void* d_out, int out_size)
{
    const float* query = (const float*)d_in[0];
    const float* key   = (const float*)d_in[1];
    const float* value = (const float*)d_in[2];
    const float* Wq    = (const float*)d_in[3];
    const float* Wk    = (const float*)d_in[4];
    const float* Wv    = (const float*)d_in[5];
    const float* Wo    = (const float*)d_in[6];
    const float* bo    = (const float*)d_in[7];
    float* out = (float*)d_out;

    static bool attr_done = false;
    if (!attr_done) {
        cudaFuncSetAttribute(gemm_mma, cudaFuncAttributeMaxDynamicSharedMemorySize, SMEM_GEMM);
        cudaFuncSetAttribute(attn_mma, cudaFuncAttributeMaxDynamicSharedMemorySize, SMEM_ATT);
        attr_done = true;
    }

    const int ntot = 3*N4X + N4W;
    split_all<<<(ntot + 255)/256, 256>>>(query, key, value, Wo);
    conv_w<<<dim3(D_/32, DK_/32, 3*H_), dim3(32, 8)>>>(Wq, Wk, Wv);

    gemm_mma<<<dim3(HD_/128, BS_/128, 3), 256, SMEM_GEMM>>>(nullptr, nullptr, 0);

    attn_mma<<<dim3(S_/128, B_*H_), 256, SMEM_ATT>>>();

    gemm_mma<<<dim3(D_/128, BS_/128, 1), 256, SMEM_GEMM>>>(bo, out, 1);
}